// round 6
// baseline (speedup 1.0000x reference)
#include <cuda_runtime.h>
#include <stdint.h>
#include <math.h>

// Problem constants
#define BATCH 512
#define NIN   256
#define EMB   256
#define HID   512
#define VOC   32000
#define TT    32
#define G3    1536          // 3*HID
#define NCHUNK 250          // VOC / 128
#define BT    (BATCH*TT)
#define F_TINY 1.17549435e-38f

// ---------------- device scratch (no allocations allowed) ----------------
__device__ float g_hA[BATCH*HID];
__device__ float g_hB[BATCH*HID];
__device__ float g_hH[BATCH*HID];     // tf32-hi of current h
__device__ float g_hL[BATCH*HID];     // tf32-lo of current h
__device__ float g_WoH[VOC*HID];      // tf32-hi of W_out (split once per launch)
__device__ float g_WoL[VOC*HID];
__device__ float g_inp[BATCH*EMB];
__device__ float g_gi[BATCH*G3];
__device__ float g_gh[BATCH*G3];
__device__ float g_pmg[BATCH*NCHUNK];
__device__ int   g_pidx[BATCH*NCHUNK];
__device__ float g_pml[BATCH*NCHUNK];
__device__ float g_pZ[BATCH*NCHUNK];
__device__ float g_pS[BATCH*NCHUNK];

// ---------------- threefry2x32 (matches jax exactly) ----------------
__device__ __forceinline__ void tf2x32(unsigned k0, unsigned k1,
                                       unsigned c0, unsigned c1,
                                       unsigned &o0, unsigned &o1) {
  unsigned ks2 = k0 ^ k1 ^ 0x1BD11BDAu;
  unsigned x0 = c0 + k0, x1 = c1 + k1;
#define TFR(r) { x0 += x1; x1 = (x1 << (r)) | (x1 >> (32 - (r))); x1 ^= x0; }
  TFR(13) TFR(15) TFR(26) TFR(6)   x0 += k1;  x1 += ks2 + 1u;
  TFR(17) TFR(29) TFR(16) TFR(24)  x0 += ks2; x1 += k0 + 2u;
  TFR(13) TFR(15) TFR(26) TFR(6)   x0 += k0;  x1 += k1 + 3u;
  TFR(17) TFR(29) TFR(16) TFR(24)  x0 += k1;  x1 += ks2 + 4u;
  TFR(13) TFR(15) TFR(26) TFR(6)   x0 += ks2; x1 += k0 + 5u;
#undef TFR
  o0 = x0; o1 = x1;
}

static void h_tf2x32(unsigned k0, unsigned k1, unsigned c0, unsigned c1,
                     unsigned *o0, unsigned *o1) {
  unsigned ks2 = k0 ^ k1 ^ 0x1BD11BDAu;
  unsigned x0 = c0 + k0, x1 = c1 + k1;
#define TFRH(r) { x0 += x1; x1 = (x1 << (r)) | (x1 >> (32 - (r))); x1 ^= x0; }
  TFRH(13) TFRH(15) TFRH(26) TFRH(6)   x0 += k1;  x1 += ks2 + 1u;
  TFRH(17) TFRH(29) TFRH(16) TFRH(24)  x0 += ks2; x1 += k0 + 2u;
  TFRH(13) TFRH(15) TFRH(26) TFRH(6)   x0 += k0;  x1 += k1 + 3u;
  TFRH(17) TFRH(29) TFRH(16) TFRH(24)  x0 += k1;  x1 += ks2 + 4u;
  TFRH(13) TFRH(15) TFRH(26) TFRH(6)   x0 += ks2; x1 += k0 + 5u;
#undef TFRH
  *o0 = x0; *o1 = x1;
}

// ---------------- tf32 helpers ----------------
__device__ __forceinline__ unsigned f2tf(float f) {
  unsigned r; asm("cvt.rna.tf32.f32 %0, %1;" : "=r"(r) : "f"(f)); return r;
}
__device__ __forceinline__ void mma8(float c[4], const unsigned a[4], const unsigned b[2]) {
  asm volatile("mma.sync.aligned.m16n8k8.row.col.f32.tf32.tf32.f32 "
               "{%0,%1,%2,%3}, {%4,%5,%6,%7}, {%8,%9}, {%0,%1,%2,%3};"
               : "+f"(c[0]), "+f"(c[1]), "+f"(c[2]), "+f"(c[3])
               : "r"(a[0]), "r"(a[1]), "r"(a[2]), "r"(a[3]),
                 "r"(b[0]), "r"(b[1]));
}
__device__ __forceinline__ void cp16(unsigned smem_addr, const void* gptr) {
  asm volatile("cp.async.ca.shared.global [%0], [%1], 16;"
               :: "r"(smem_addr), "l"(gptr));
}

// ---------------- W_out splitter (once per launch) ----------------
__global__ __launch_bounds__(256)
void split_kernel(const float* __restrict__ src, float* __restrict__ hi,
                  float* __restrict__ lo) {
  int i = blockIdx.x * blockDim.x + threadIdx.x;   // over float4s
  float4 v = ((const float4*)src)[i];
  float4 h4, l4;
  h4.x = __uint_as_float(f2tf(v.x)); l4.x = __uint_as_float(f2tf(v.x - h4.x));
  h4.y = __uint_as_float(f2tf(v.y)); l4.y = __uint_as_float(f2tf(v.y - h4.y));
  h4.z = __uint_as_float(f2tf(v.z)); l4.z = __uint_as_float(f2tf(v.z - h4.z));
  h4.w = __uint_as_float(f2tf(v.w)); l4.w = __uint_as_float(f2tf(v.w - h4.w));
  ((float4*)hi)[i] = h4;
  ((float4*)lo)[i] = l4;
}

// ---------------- shared SGEMM mainloop (C = A[M,K] @ B[N,K]^T) ----------
#define SGEMM_MAINLOOP(A, Bm, K)                                             \
  float acc[8][4];                                                           \
  _Pragma("unroll")                                                          \
  for (int i = 0; i < 8; i++) { _Pragma("unroll")                            \
    for (int j = 0; j < 4; j++) acc[i][j] = 0.f; }                           \
  {                                                                          \
    const float* Aptr = (A) + (size_t)rowBase * (K);                         \
    const float* Bptr = (Bm) + (size_t)colBase * (K);                        \
    int ar = tid >> 2, akq = tid & 3;                                        \
    for (int k0 = 0; k0 < (K); k0 += 16) {                                   \
      float4 av = *(const float4*)(Aptr + (size_t)ar * (K) + k0 + akq * 4);  \
      As[akq*4+0][ar] = av.x; As[akq*4+1][ar] = av.y;                        \
      As[akq*4+2][ar] = av.z; As[akq*4+3][ar] = av.w;                        \
      _Pragma("unroll")                                                      \
      for (int li = 0; li < 2; li++) {                                       \
        int idx2 = tid + li * 256; int br = idx2 >> 2, bkq = idx2 & 3;       \
        float4 bv = *(const float4*)(Bptr + (size_t)br * (K) + k0 + bkq*4);  \
        Bs[bkq*4+0][br] = bv.x; Bs[bkq*4+1][br] = bv.y;                      \
        Bs[bkq*4+2][br] = bv.z; Bs[bkq*4+3][br] = bv.w;                      \
      }                                                                      \
      __syncthreads();                                                       \
      _Pragma("unroll")                                                      \
      for (int kk = 0; kk < 16; kk++) {                                      \
        float a[8];                                                          \
        _Pragma("unroll")                                                    \
        for (int i = 0; i < 8; i++) a[i] = As[kk][ry*8+i];                   \
        float4 bq = *(const float4*)(&Bs[kk][cx*4]);                         \
        float bb[4] = {bq.x, bq.y, bq.z, bq.w};                              \
        _Pragma("unroll")                                                    \
        for (int i = 0; i < 8; i++) { _Pragma("unroll")                      \
          for (int j = 0; j < 4; j++) acc[i][j] += a[i] * bb[j]; }           \
      }                                                                      \
      __syncthreads();                                                       \
    }                                                                        \
  }

__global__ __launch_bounds__(256)
void sgemm_bias_kernel(const float* __restrict__ A, const float* __restrict__ Bm,
                       const float* __restrict__ bias, float* __restrict__ C,
                       int K, int N) {
  __shared__ __align__(16) float As[16][65];
  __shared__ __align__(16) float Bs[16][132];
  int tid = threadIdx.x;
  int cx = tid & 31, ry = tid >> 5;
  int rowBase = blockIdx.y * 64;
  int colBase = blockIdx.x * 128;
  SGEMM_MAINLOOP(A, Bm, K)
  int col = colBase + cx * 4;
  float4 b4 = *(const float4*)(bias + col);
#pragma unroll
  for (int i = 0; i < 8; i++) {
    int row = rowBase + ry * 8 + i;
    float4 o;
    o.x = acc[i][0] + b4.x; o.y = acc[i][1] + b4.y;
    o.z = acc[i][2] + b4.z; o.w = acc[i][3] + b4.w;
    *(float4*)(C + (size_t)row * N + col) = o;
  }
}

// Both small GRU GEMMs in one launch: z=0 -> gi = inp@W_ih^T+b_ih (K=256)
//                                     z=1 -> gh = h  @W_hh^T+b_hh (K=512)
__global__ __launch_bounds__(256)
void dual_sgemm_kernel(const float* __restrict__ inp, const float* __restrict__ W_ih,
                       const float* __restrict__ b_ih, float* __restrict__ gi,
                       const float* __restrict__ hp, const float* __restrict__ W_hh,
                       const float* __restrict__ b_hh, float* __restrict__ gh) {
  __shared__ __align__(16) float As[16][65];
  __shared__ __align__(16) float Bs[16][132];
  int tid = threadIdx.x;
  int cx = tid & 31, ry = tid >> 5;
  int rowBase = blockIdx.y * 64;
  int colBase = blockIdx.x * 128;
  const float* A  = blockIdx.z ? hp   : inp;
  const float* Bm = blockIdx.z ? W_hh : W_ih;
  const float* bias = blockIdx.z ? b_hh : b_ih;
  float* C = blockIdx.z ? gh : gi;
  const int K = blockIdx.z ? HID : NIN;
  SGEMM_MAINLOOP(A, Bm, K)
  int col = colBase + cx * 4;
  float4 b4 = *(const float4*)(bias + col);
#pragma unroll
  for (int i = 0; i < 8; i++) {
    int row = rowBase + ry * 8 + i;
    float4 o;
    o.x = acc[i][0] + b4.x; o.y = acc[i][1] + b4.y;
    o.z = acc[i][2] + b4.z; o.w = acc[i][3] + b4.w;
    *(float4*)(C + (size_t)row * G3 + col) = o;
  }
}

// ================= logits GEMM: 3xTF32 mma.sync, pre-split operands =======
// M=512, N=32000, K=512. CTA 128x128, BK=16, 8 warps (2x4), warp 64x32.
// Double-buffered cp.async staging; fused gumbel/softmax epilogue.
#define NKIT (HID/16)
__global__ __launch_bounds__(256)
void logits_mma_kernel(const float* __restrict__ AH, const float* __restrict__ AL,
                       const float* __restrict__ BH, const float* __restrict__ BL,
                       const float* __restrict__ bias,
                       float* __restrict__ pmg, int* __restrict__ pidx,
                       float* __restrict__ pml, float* __restrict__ pZ,
                       float* __restrict__ pS,
                       unsigned k1a, unsigned k1b) {
  extern __shared__ __align__(16) unsigned dsm[];   // 2 stages x 10240 uint

  const int tid = threadIdx.x;
  const int lane = tid & 31, wid = tid >> 5;
  const int wm = wid >> 2;       // 0..1
  const int wn = wid & 3;        // 0..3
  const int qr = lane >> 2;      // 0..7
  const int qc = lane & 3;       // 0..3
  const int rowBase = blockIdx.y * 128;
  const int colBase = blockIdx.x * 128;

  // per-thread cp.async assignments: 8 chunks of 16B per stage
  // chunk id = tid + i*256 ; tile = id>>9 (0:AH 1:AL 2:BH 3:BL), row=(id>>2)&127, kq=id&3
  const float* srcs[4];
  srcs[0] = AH + (size_t)rowBase * HID;
  srcs[1] = AL + (size_t)rowBase * HID;
  srcs[2] = BH + (size_t)colBase * HID;
  srcs[3] = BL + (size_t)colBase * HID;

  unsigned smem_base_u32 = (unsigned)__cvta_generic_to_shared(dsm);

  float acc[4][4][4];
#pragma unroll
  for (int mt = 0; mt < 4; mt++)
#pragma unroll
    for (int nt = 0; nt < 4; nt++)
#pragma unroll
      for (int r = 0; r < 4; r++) acc[mt][nt][r] = 0.f;

  // issue loads for stage s, k-offset k0
  auto load_stage = [&](int s, int k0) {
#pragma unroll
    for (int i = 0; i < 8; i++) {
      int id = tid + i * 256;
      int tile = id >> 9, row = (id >> 2) & 127, kq = id & 3;
      const float* g = srcs[tile] + (size_t)row * HID + k0 + kq * 4;
      unsigned sa = smem_base_u32 + (s * 10240 + tile * 2560 + row * 20 + kq * 4) * 4;
      cp16(sa, g);
    }
    asm volatile("cp.async.commit_group;");
  };

  load_stage(0, 0);
  for (int it = 0; it < NKIT; it++) {
    int cur = it & 1;
    if (it + 1 < NKIT) {
      load_stage(cur ^ 1, (it + 1) * 16);
      asm volatile("cp.async.wait_group 1;");
    } else {
      asm volatile("cp.async.wait_group 0;");
    }
    __syncthreads();
    const unsigned* AsH = dsm + cur * 10240;
    const unsigned* AsL = AsH + 2560;
    const unsigned* BsH = AsH + 5120;
    const unsigned* BsL = AsH + 7680;
#pragma unroll
    for (int ks = 0; ks < 16; ks += 8) {
      unsigned ah[4][4], al[4][4], bh[4][2], bl[4][2];
#pragma unroll
      for (int mt = 0; mt < 4; mt++) {
        int r0 = (wm * 64 + mt * 16 + qr) * 20 + ks + qc;
        int r1 = r0 + 8 * 20;
        ah[mt][0] = AsH[r0];     ah[mt][1] = AsH[r1];
        ah[mt][2] = AsH[r0 + 4]; ah[mt][3] = AsH[r1 + 4];
        al[mt][0] = AsL[r0];     al[mt][1] = AsL[r1];
        al[mt][2] = AsL[r0 + 4]; al[mt][3] = AsL[r1 + 4];
      }
#pragma unroll
      for (int nt = 0; nt < 4; nt++) {
        int c0 = (wn * 32 + nt * 8 + qr) * 20 + ks + qc;
        bh[nt][0] = BsH[c0]; bh[nt][1] = BsH[c0 + 4];
        bl[nt][0] = BsL[c0]; bl[nt][1] = BsL[c0 + 4];
      }
#pragma unroll
      for (int mt = 0; mt < 4; mt++)
#pragma unroll
        for (int nt = 0; nt < 4; nt++) {
          mma8(acc[mt][nt], ah[mt], bl[nt]);   // small terms first
          mma8(acc[mt][nt], al[mt], bh[nt]);
          mma8(acc[mt][nt], ah[mt], bh[nt]);
        }
    }
    __syncthreads();
  }

  // ---------- fused epilogue ----------
  float bcol[8]; int colg[8];
#pragma unroll
  for (int j = 0; j < 8; j++) {
    int nt = j >> 1, cc = j & 1;
    int col = colBase + wn * 32 + nt * 8 + qc * 2 + cc;
    colg[j] = col;
    bcol[j] = bias[col];
  }
  float* rmg = (float*)dsm;            // [128][4]
  int*   rix = (int*)(dsm + 512);
  float* rml = (float*)(dsm + 1024);
  float* rZf = (float*)(dsm + 1536);
  float* rSf = (float*)(dsm + 2048);

#pragma unroll
  for (int mt = 0; mt < 4; mt++) {
#pragma unroll
    for (int rg = 0; rg < 2; rg++) {
      int lrow = wm * 64 + mt * 16 + qr + rg * 8;
      int grow = rowBase + lrow;
      float l[8];
      float lml = -INFINITY;
#pragma unroll
      for (int j = 0; j < 8; j++) {
        int nt = j >> 1, cc = j & 1;
        l[j] = acc[mt][nt][rg * 2 + cc] + bcol[j];
        lml = fmaxf(lml, l[j]);
      }
      float best = -INFINITY; int bidx = 0x7fffffff;
      float Z = 0.f, S = 0.f;
#pragma unroll
      for (int j = 0; j < 8; j++) {
        unsigned o0, o1;
        tf2x32(k1a, k1b, 0u, (unsigned)(grow * VOC + colg[j]), o0, o1);
        unsigned rb = o0 ^ o1;
        float u = __uint_as_float((rb >> 9) | 0x3f800000u) - 1.0f;
        u = fmaxf(u, F_TINY);
        float g = -logf(-logf(u));
        float v = l[j] + g;
        if (v > best) { best = v; bidx = colg[j]; }
        float e = expf(l[j] - lml);
        Z += e; S += e * l[j];
      }
#pragma unroll
      for (int off = 1; off <= 2; off <<= 1) {
        float omg = __shfl_xor_sync(0xffffffffu, best, off);
        int   oix = __shfl_xor_sync(0xffffffffu, bidx, off);
        float oml = __shfl_xor_sync(0xffffffffu, lml, off);
        float oZ  = __shfl_xor_sync(0xffffffffu, Z, off);
        float oS  = __shfl_xor_sync(0xffffffffu, S, off);
        if (omg > best || (omg == best && oix < bidx)) { best = omg; bidx = oix; }
        float M = fmaxf(lml, oml);
        float w1 = expf(lml - M), w2 = expf(oml - M);
        Z = Z * w1 + oZ * w2;
        S = S * w1 + oS * w2;
        lml = M;
      }
      if (qc == 0) {
        rmg[lrow * 4 + wn] = best; rix[lrow * 4 + wn] = bidx;
        rml[lrow * 4 + wn] = lml;  rZf[lrow * 4 + wn] = Z;
        rSf[lrow * 4 + wn] = S;
      }
    }
  }
  __syncthreads();
  if (tid < 128) {
    int lrow = tid;
    float mg = rmg[lrow * 4]; int idx = rix[lrow * 4];
    float ml = rml[lrow * 4]; float Z = rZf[lrow * 4]; float S = rSf[lrow * 4];
#pragma unroll
    for (int w = 1; w < 4; w++) {
      float omg = rmg[lrow * 4 + w]; int oix = rix[lrow * 4 + w];
      float oml = rml[lrow * 4 + w]; float oZ = rZf[lrow * 4 + w];
      float oS = rSf[lrow * 4 + w];
      if (omg > mg || (omg == mg && oix < idx)) { mg = omg; idx = oix; }
      float M = fmaxf(ml, oml);
      float w1 = expf(ml - M), w2 = expf(oml - M);
      Z = Z * w1 + oZ * w2;
      S = S * w1 + oS * w2;
      ml = M;
    }
    int pi = (rowBase + lrow) * NCHUNK + blockIdx.x;
    pmg[pi] = mg; pidx[pi] = idx; pml[pi] = ml; pZ[pi] = Z; pS[pi] = S;
  }
}

// ---------------- GRU pointwise update (+ tf32 split of h) ----------------
__device__ __forceinline__ float sigmoidf_(float x) { return 1.f / (1.f + expf(-x)); }

__global__ __launch_bounds__(256)
void gru_update_kernel(const float* __restrict__ gi, const float* __restrict__ gh,
                       const float* __restrict__ hprev, float* __restrict__ hnew,
                       float* __restrict__ hH, float* __restrict__ hL) {
  int i = blockIdx.x * blockDim.x + threadIdx.x;    // 512*512
  int b = i >> 9, j = i & 511;
  const float* gib = gi + (size_t)b * G3;
  const float* ghb = gh + (size_t)b * G3;
  float r = sigmoidf_(gib[j]        + ghb[j]);
  float z = sigmoidf_(gib[512 + j]  + ghb[512 + j]);
  float n = tanhf(gib[1024 + j] + r * ghb[1024 + j]);
  float h = (1.f - z) * n + z * hprev[i];
  hnew[i] = h;
  float hi = __uint_as_float(f2tf(h));
  hH[i] = hi;
  hL[i] = __uint_as_float(f2tf(h - hi));
}

__global__ void init_inp_kernel(const float* __restrict__ sos, float* __restrict__ inp) {
  int i = blockIdx.x * blockDim.x + threadIdx.x;    // 512*256
  inp[i] = sos[i & 255];
}

// ---------------- per-row finalize ----------------
__global__ __launch_bounds__(256)
void finalize_kernel(const float* __restrict__ h, const float* __restrict__ W_out,
                     const float* __restrict__ b_out, const float* __restrict__ W_stop,
                     const float* __restrict__ b_stop, const float* __restrict__ emb,
                     const float* __restrict__ pmg, const int* __restrict__ pidx,
                     const float* __restrict__ pml, const float* __restrict__ pZ,
                     const float* __restrict__ pS,
                     float* __restrict__ inp, float* __restrict__ out,
                     int t, unsigned k2a, unsigned k2b) {
  int b = blockIdx.x, tid = threadIdx.x;
  float mg = -INFINITY, ml = -INFINITY, Z = 0.f, S = 0.f;
  int idx = 0x7fffffff;
  if (tid < NCHUNK) {
    int p = b * NCHUNK + tid;
    mg = pmg[p]; idx = pidx[p]; ml = pml[p]; Z = pZ[p]; S = pS[p];
  }
#pragma unroll
  for (int off = 16; off > 0; off >>= 1) {
    float omg = __shfl_xor_sync(0xffffffffu, mg, off);
    int   oix = __shfl_xor_sync(0xffffffffu, idx, off);
    float oml = __shfl_xor_sync(0xffffffffu, ml, off);
    float oZ  = __shfl_xor_sync(0xffffffffu, Z, off);
    float oS  = __shfl_xor_sync(0xffffffffu, S, off);
    if (omg > mg || (omg == mg && oix < idx)) { mg = omg; idx = oix; }
    float M = fmaxf(ml, oml);
    if (M > -INFINITY) {
      float w1 = (ml  > -INFINITY) ? expf(ml  - M) : 0.f;
      float w2 = (oml > -INFINITY) ? expf(oml - M) : 0.f;
      Z = Z * w1 + oZ * w2;
      S = S * w1 + oS * w2;
      ml = M;
    }
  }
  __shared__ float smg[8]; __shared__ int sidx[8];
  __shared__ float sml[8], sZ[8], sS[8];
  __shared__ int s_symb; __shared__ float s_ml, s_Z, s_S;
  int wid = tid >> 5, lane = tid & 31;
  if (lane == 0) { smg[wid] = mg; sidx[wid] = idx; sml[wid] = ml; sZ[wid] = Z; sS[wid] = S; }
  __syncthreads();
  if (wid == 0) {
    if (lane < 8) { mg = smg[lane]; idx = sidx[lane]; ml = sml[lane]; Z = sZ[lane]; S = sS[lane]; }
    else { mg = -INFINITY; idx = 0x7fffffff; ml = -INFINITY; Z = 0.f; S = 0.f; }
#pragma unroll
    for (int off = 4; off > 0; off >>= 1) {
      float omg = __shfl_xor_sync(0xffffffffu, mg, off);
      int   oix = __shfl_xor_sync(0xffffffffu, idx, off);
      float oml = __shfl_xor_sync(0xffffffffu, ml, off);
      float oZ  = __shfl_xor_sync(0xffffffffu, Z, off);
      float oS  = __shfl_xor_sync(0xffffffffu, S, off);
      if (omg > mg || (omg == mg && oix < idx)) { mg = omg; idx = oix; }
      float M = fmaxf(ml, oml);
      if (M > -INFINITY) {
        float w1 = (ml  > -INFINITY) ? expf(ml  - M) : 0.f;
        float w2 = (oml > -INFINITY) ? expf(oml - M) : 0.f;
        Z = Z * w1 + oZ * w2;
        S = S * w1 + oS * w2;
        ml = M;
      }
    }
    if (lane == 0) { s_symb = idx; s_ml = ml; s_Z = Z; s_S = S; }
  }
  __syncthreads();
  int symb = s_symb;

  __shared__ float r1[256], r2[256];
  float a1 = 0.f, a2 = 0.f;
  const float* hrow = h + (size_t)b * HID;
  const float* wrow = W_out + (size_t)symb * HID;
#pragma unroll
  for (int k = tid; k < HID; k += 256) {
    float hv = hrow[k];
    a1 += hv * wrow[k];
    a2 += hv * W_stop[k];
  }
  r1[tid] = a1; r2[tid] = a2;
  __syncthreads();
  for (int s = 128; s > 0; s >>= 1) {
    if (tid < s) { r1[tid] += r1[tid + s]; r2[tid] += r2[tid + s]; }
    __syncthreads();
  }

  inp[(size_t)b * EMB + tid] = emb[(size_t)symb * EMB + tid];

  if (tid == 0) {
    float lse = s_ml + logf(s_Z);
    float ent = lse - s_S / s_Z;
    float lsymb = r1[0] + b_out[symb];
    float sl = r2[0] + b_stop[0];
    unsigned o0, o1;
    tf2x32(k2a, k2b, 0u, (unsigned)b, o0, o1);
    unsigned rb = o0 ^ o1;
    float u = __uint_as_float((rb >> 9) | 0x3f800000u) - 1.0f;
    float p = 1.f / (1.f + expf(-sl));
    int stop = (u < p) ? 1 : 0;
    float sp = fmaxf(sl, 0.f) + log1pf(expf(-fabsf(sl)));
    out[0 * BT + b * TT + t] = (float)symb;
    out[1 * BT + b * TT + t] = (float)stop;
    out[2 * BT + b * TT + t] = lsymb - lse;
    out[3 * BT + b * TT + t] = (float)stop * sl - sp;
    out[4 * BT + b * TT + t] = ent;
    out[5 * BT + b * TT + t] = sp - sl * p;
  }
}

// ---------------- host ----------------
extern "C" void kernel_launch(void* const* d_in, const int* in_sizes, int n_in,
                              void* d_out, int out_size) {
  const float* x       = (const float*)d_in[0];
  const float* agent_w = (const float*)d_in[1];
  const float* agent_b = (const float*)d_in[2];
  const float* sos     = (const float*)d_in[3];
  const float* emb     = (const float*)d_in[4];
  const float* W_ih    = (const float*)d_in[5];
  const float* W_hh    = (const float*)d_in[6];
  const float* b_ih    = (const float*)d_in[7];
  const float* b_hh    = (const float*)d_in[8];
  const float* W_out   = (const float*)d_in[9];
  const float* b_out   = (const float*)d_in[10];
  const float* W_stop  = (const float*)d_in[11];
  const float* b_stop  = (const float*)d_in[12];
  float* out = (float*)d_out;

  float *hA, *hB, *hH, *hL, *WoH, *WoL, *inp, *gi, *gh, *pmg, *pml, *pZ, *pS;
  int* pidx;
  cudaGetSymbolAddress((void**)&hA,  g_hA);
  cudaGetSymbolAddress((void**)&hB,  g_hB);
  cudaGetSymbolAddress((void**)&hH,  g_hH);
  cudaGetSymbolAddress((void**)&hL,  g_hL);
  cudaGetSymbolAddress((void**)&WoH, g_WoH);
  cudaGetSymbolAddress((void**)&WoL, g_WoL);
  cudaGetSymbolAddress((void**)&inp, g_inp);
  cudaGetSymbolAddress((void**)&gi,  g_gi);
  cudaGetSymbolAddress((void**)&gh,  g_gh);
  cudaGetSymbolAddress((void**)&pmg, g_pmg);
  cudaGetSymbolAddress((void**)&pidx, g_pidx);
  cudaGetSymbolAddress((void**)&pml, g_pml);
  cudaGetSymbolAddress((void**)&pZ,  g_pZ);
  cudaGetSymbolAddress((void**)&pS,  g_pS);

  cudaFuncSetAttribute(logits_mma_kernel,
                       cudaFuncAttributeMaxDynamicSharedMemorySize, 81920);

  // one-time per launch: split W_out into tf32 hi/lo
  split_kernel<<<(VOC * HID / 4) / 256, 256>>>(W_out, WoH, WoL);

  sgemm_bias_kernel<<<dim3(HID / 128, BATCH / 64), 256>>>(x, agent_w, agent_b, hA, NIN, HID);
  init_inp_kernel<<<(BATCH * EMB) / 256, 256>>>(sos, inp);

  for (int t = 0; t < TT; t++) {
    unsigned kt0, kt1, k1a, k1b, k2a, k2b;
    h_tf2x32(0u, 42u, 0u, (unsigned)t, &kt0, &kt1);
    h_tf2x32(kt0, kt1, 0u, 0u, &k1a, &k1b);
    h_tf2x32(kt0, kt1, 0u, 1u, &k2a, &k2b);

    const float* hp = (t & 1) ? hB : hA;
    float*       hn = (t & 1) ? hA : hB;

    dual_sgemm_kernel<<<dim3(G3 / 128, BATCH / 64, 2), 256>>>(
        inp, W_ih, b_ih, gi, hp, W_hh, b_hh, gh);
    gru_update_kernel<<<(BATCH * HID) / 256, 256>>>(gi, gh, hp, hn, hH, hL);
    logits_mma_kernel<<<dim3(VOC / 128, BATCH / 128), 256, 81920>>>(
        hH, hL, WoH, WoL, b_out, pmg, pidx, pml, pZ, pS, k1a, k1b);
    finalize_kernel<<<BATCH, 256>>>(hn, W_out, b_out, W_stop, b_stop, emb,
                                    pmg, pidx, pml, pZ, pS, inp, out, t, k2a, k2b);
  }
}

// round 10
// speedup vs baseline: 1.0089x; 1.0089x over previous
#include <cuda_runtime.h>
#include <stdint.h>
#include <math.h>

// Problem constants
#define BATCH 512
#define NIN   256
#define EMB   256
#define HID   512
#define VOC   32000
#define TT    32
#define G3    1536          // 3*HID
#define NCHUNK 250          // VOC / 128
#define BT    (BATCH*TT)
#define F_TINY 1.17549435e-38f

// ---------------- device scratch (no allocations allowed) ----------------
__device__ float g_hA[BATCH*HID];
__device__ float g_hB[BATCH*HID];
__device__ float g_hH[BATCH*HID];     // tf32-hi of current h
__device__ float g_hL[BATCH*HID];     // tf32-lo of current h
__device__ float g_WoH[VOC*HID];      // tf32-hi of W_out (split once per launch)
__device__ float g_WoL[VOC*HID];
__device__ float g_inp[BATCH*EMB];
__device__ float g_gi[BATCH*G3];
__device__ float g_gh[BATCH*G3];
__device__ float g_pmg[BATCH*NCHUNK];
__device__ int   g_pidx[BATCH*NCHUNK];
__device__ float g_pml[BATCH*NCHUNK];
__device__ float g_pZ[BATCH*NCHUNK];
__device__ float g_pS[BATCH*NCHUNK];

// ---------------- threefry2x32 (matches jax exactly) ----------------
__device__ __forceinline__ void tf2x32(unsigned k0, unsigned k1,
                                       unsigned c0, unsigned c1,
                                       unsigned &o0, unsigned &o1) {
  unsigned ks2 = k0 ^ k1 ^ 0x1BD11BDAu;
  unsigned x0 = c0 + k0, x1 = c1 + k1;
#define TFR(r) { x0 += x1; x1 = (x1 << (r)) | (x1 >> (32 - (r))); x1 ^= x0; }
  TFR(13) TFR(15) TFR(26) TFR(6)   x0 += k1;  x1 += ks2 + 1u;
  TFR(17) TFR(29) TFR(16) TFR(24)  x0 += ks2; x1 += k0 + 2u;
  TFR(13) TFR(15) TFR(26) TFR(6)   x0 += k0;  x1 += k1 + 3u;
  TFR(17) TFR(29) TFR(16) TFR(24)  x0 += k1;  x1 += ks2 + 4u;
  TFR(13) TFR(15) TFR(26) TFR(6)   x0 += ks2; x1 += k0 + 5u;
#undef TFR
  o0 = x0; o1 = x1;
}

static void h_tf2x32(unsigned k0, unsigned k1, unsigned c0, unsigned c1,
                     unsigned *o0, unsigned *o1) {
  unsigned ks2 = k0 ^ k1 ^ 0x1BD11BDAu;
  unsigned x0 = c0 + k0, x1 = c1 + k1;
#define TFRH(r) { x0 += x1; x1 = (x1 << (r)) | (x1 >> (32 - (r))); x1 ^= x0; }
  TFRH(13) TFRH(15) TFRH(26) TFRH(6)   x0 += k1;  x1 += ks2 + 1u;
  TFRH(17) TFRH(29) TFRH(16) TFRH(24)  x0 += ks2; x1 += k0 + 2u;
  TFRH(13) TFRH(15) TFRH(26) TFRH(6)   x0 += k0;  x1 += k1 + 3u;
  TFRH(17) TFRH(29) TFRH(16) TFRH(24)  x0 += k1;  x1 += ks2 + 4u;
  TFRH(13) TFRH(15) TFRH(26) TFRH(6)   x0 += ks2; x1 += k0 + 5u;
#undef TFRH
  *o0 = x0; *o1 = x1;
}

// ---------------- tf32 helpers ----------------
__device__ __forceinline__ unsigned f2tf(float f) {
  unsigned r; asm("cvt.rna.tf32.f32 %0, %1;" : "=r"(r) : "f"(f)); return r;
}
__device__ __forceinline__ void mma8(float c[4], const unsigned a[4], const unsigned b[2]) {
  asm volatile("mma.sync.aligned.m16n8k8.row.col.f32.tf32.tf32.f32 "
               "{%0,%1,%2,%3}, {%4,%5,%6,%7}, {%8,%9}, {%0,%1,%2,%3};"
               : "+f"(c[0]), "+f"(c[1]), "+f"(c[2]), "+f"(c[3])
               : "r"(a[0]), "r"(a[1]), "r"(a[2]), "r"(a[3]),
                 "r"(b[0]), "r"(b[1]));
}
__device__ __forceinline__ void cp16(unsigned smem_addr, const void* gptr) {
  asm volatile("cp.async.ca.shared.global [%0], [%1], 16;"
               :: "r"(smem_addr), "l"(gptr));
}

// ---------------- W_out splitter (once per launch) ----------------
__global__ __launch_bounds__(256)
void split_kernel(const float* __restrict__ src, float* __restrict__ hi,
                  float* __restrict__ lo) {
  int i = blockIdx.x * blockDim.x + threadIdx.x;   // over float4s
  float4 v = ((const float4*)src)[i];
  float4 h4, l4;
  h4.x = __uint_as_float(f2tf(v.x)); l4.x = __uint_as_float(f2tf(v.x - h4.x));
  h4.y = __uint_as_float(f2tf(v.y)); l4.y = __uint_as_float(f2tf(v.y - h4.y));
  h4.z = __uint_as_float(f2tf(v.z)); l4.z = __uint_as_float(f2tf(v.z - h4.z));
  h4.w = __uint_as_float(f2tf(v.w)); l4.w = __uint_as_float(f2tf(v.w - h4.w));
  ((float4*)hi)[i] = h4;
  ((float4*)lo)[i] = l4;
}

// ---------------- shared SGEMM mainloop (C = A[M,K] @ B[N,K]^T) ----------
#define SGEMM_MAINLOOP(A, Bm, K)                                             \
  float acc[8][4];                                                           \
  _Pragma("unroll")                                                          \
  for (int i = 0; i < 8; i++) { _Pragma("unroll")                            \
    for (int j = 0; j < 4; j++) acc[i][j] = 0.f; }                           \
  {                                                                          \
    const float* Aptr = (A) + (size_t)rowBase * (K);                         \
    const float* Bptr = (Bm) + (size_t)colBase * (K);                        \
    int ar = tid >> 2, akq = tid & 3;                                        \
    for (int k0 = 0; k0 < (K); k0 += 16) {                                   \
      float4 av = *(const float4*)(Aptr + (size_t)ar * (K) + k0 + akq * 4);  \
      As[akq*4+0][ar] = av.x; As[akq*4+1][ar] = av.y;                        \
      As[akq*4+2][ar] = av.z; As[akq*4+3][ar] = av.w;                        \
      _Pragma("unroll")                                                      \
      for (int li = 0; li < 2; li++) {                                       \
        int idx2 = tid + li * 256; int br = idx2 >> 2, bkq = idx2 & 3;       \
        float4 bv = *(const float4*)(Bptr + (size_t)br * (K) + k0 + bkq*4);  \
        Bs[bkq*4+0][br] = bv.x; Bs[bkq*4+1][br] = bv.y;                      \
        Bs[bkq*4+2][br] = bv.z; Bs[bkq*4+3][br] = bv.w;                      \
      }                                                                      \
      __syncthreads();                                                       \
      _Pragma("unroll")                                                      \
      for (int kk = 0; kk < 16; kk++) {                                      \
        float a[8];                                                          \
        _Pragma("unroll")                                                    \
        for (int i = 0; i < 8; i++) a[i] = As[kk][ry*8+i];                   \
        float4 bq = *(const float4*)(&Bs[kk][cx*4]);                         \
        float bb[4] = {bq.x, bq.y, bq.z, bq.w};                              \
        _Pragma("unroll")                                                    \
        for (int i = 0; i < 8; i++) { _Pragma("unroll")                      \
          for (int j = 0; j < 4; j++) acc[i][j] += a[i] * bb[j]; }           \
      }                                                                      \
      __syncthreads();                                                       \
    }                                                                        \
  }

__global__ __launch_bounds__(256)
void sgemm_bias_kernel(const float* __restrict__ A, const float* __restrict__ Bm,
                       const float* __restrict__ bias, float* __restrict__ C,
                       int K, int N) {
  __shared__ __align__(16) float As[16][65];
  __shared__ __align__(16) float Bs[16][132];
  int tid = threadIdx.x;
  int cx = tid & 31, ry = tid >> 5;
  int rowBase = blockIdx.y * 64;
  int colBase = blockIdx.x * 128;
  SGEMM_MAINLOOP(A, Bm, K)
  int col = colBase + cx * 4;
  float4 b4 = *(const float4*)(bias + col);
#pragma unroll
  for (int i = 0; i < 8; i++) {
    int row = rowBase + ry * 8 + i;
    float4 o;
    o.x = acc[i][0] + b4.x; o.y = acc[i][1] + b4.y;
    o.z = acc[i][2] + b4.z; o.w = acc[i][3] + b4.w;
    *(float4*)(C + (size_t)row * N + col) = o;
  }
}

// Both small GRU GEMMs in one launch: z=0 -> gi = inp@W_ih^T+b_ih (K=256)
//                                     z=1 -> gh = h  @W_hh^T+b_hh (K=512)
__global__ __launch_bounds__(256)
void dual_sgemm_kernel(const float* __restrict__ inp, const float* __restrict__ W_ih,
                       const float* __restrict__ b_ih, float* __restrict__ gi,
                       const float* __restrict__ hp, const float* __restrict__ W_hh,
                       const float* __restrict__ b_hh, float* __restrict__ gh) {
  __shared__ __align__(16) float As[16][65];
  __shared__ __align__(16) float Bs[16][132];
  int tid = threadIdx.x;
  int cx = tid & 31, ry = tid >> 5;
  int rowBase = blockIdx.y * 64;
  int colBase = blockIdx.x * 128;
  const float* A  = blockIdx.z ? hp   : inp;
  const float* Bm = blockIdx.z ? W_hh : W_ih;
  const float* bias = blockIdx.z ? b_hh : b_ih;
  float* C = blockIdx.z ? gh : gi;
  const int K = blockIdx.z ? HID : NIN;
  SGEMM_MAINLOOP(A, Bm, K)
  int col = colBase + cx * 4;
  float4 b4 = *(const float4*)(bias + col);
#pragma unroll
  for (int i = 0; i < 8; i++) {
    int row = rowBase + ry * 8 + i;
    float4 o;
    o.x = acc[i][0] + b4.x; o.y = acc[i][1] + b4.y;
    o.z = acc[i][2] + b4.z; o.w = acc[i][3] + b4.w;
    *(float4*)(C + (size_t)row * G3 + col) = o;
  }
}

// ================= logits GEMM: 3xTF32 mma.sync, pre-split operands =======
// M=512, N=32000, K=512. CTA 128x128, BK=16, 8 warps (2x4), warp 64x32.
// Double-buffered cp.async staging; fused gumbel/softmax epilogue.
#define NKIT (HID/16)
__global__ __launch_bounds__(256)
void logits_mma_kernel(const float* __restrict__ AH, const float* __restrict__ AL,
                       const float* __restrict__ BH, const float* __restrict__ BL,
                       const float* __restrict__ bias,
                       float* __restrict__ pmg, int* __restrict__ pidx,
                       float* __restrict__ pml, float* __restrict__ pZ,
                       float* __restrict__ pS,
                       unsigned k1a, unsigned k1b) {
  extern __shared__ __align__(16) unsigned dsm[];   // 2 stages x 10240 uint

  const int tid = threadIdx.x;
  const int lane = tid & 31, wid = tid >> 5;
  const int wm = wid >> 2;       // 0..1
  const int wn = wid & 3;        // 0..3
  const int qr = lane >> 2;      // 0..7
  const int qc = lane & 3;       // 0..3
  const int rowBase = blockIdx.y * 128;
  const int colBase = blockIdx.x * 128;

  // per-thread cp.async assignments: 8 chunks of 16B per stage
  // chunk id = tid + i*256 ; tile = id>>9 (0:AH 1:AL 2:BH 3:BL), row=(id>>2)&127, kq=id&3
  const float* srcs[4];
  srcs[0] = AH + (size_t)rowBase * HID;
  srcs[1] = AL + (size_t)rowBase * HID;
  srcs[2] = BH + (size_t)colBase * HID;
  srcs[3] = BL + (size_t)colBase * HID;

  unsigned smem_base_u32 = (unsigned)__cvta_generic_to_shared(dsm);

  float acc[4][4][4];
#pragma unroll
  for (int mt = 0; mt < 4; mt++)
#pragma unroll
    for (int nt = 0; nt < 4; nt++)
#pragma unroll
      for (int r = 0; r < 4; r++) acc[mt][nt][r] = 0.f;

  // issue loads for stage s, k-offset k0
  auto load_stage = [&](int s, int k0) {
#pragma unroll
    for (int i = 0; i < 8; i++) {
      int id = tid + i * 256;
      int tile = id >> 9, row = (id >> 2) & 127, kq = id & 3;
      const float* g = srcs[tile] + (size_t)row * HID + k0 + kq * 4;
      unsigned sa = smem_base_u32 + (s * 10240 + tile * 2560 + row * 20 + kq * 4) * 4;
      cp16(sa, g);
    }
    asm volatile("cp.async.commit_group;");
  };

  load_stage(0, 0);
  for (int it = 0; it < NKIT; it++) {
    int cur = it & 1;
    if (it + 1 < NKIT) {
      load_stage(cur ^ 1, (it + 1) * 16);
      asm volatile("cp.async.wait_group 1;");
    } else {
      asm volatile("cp.async.wait_group 0;");
    }
    __syncthreads();
    const unsigned* AsH = dsm + cur * 10240;
    const unsigned* AsL = AsH + 2560;
    const unsigned* BsH = AsH + 5120;
    const unsigned* BsL = AsH + 7680;
#pragma unroll
    for (int ks = 0; ks < 16; ks += 8) {
      unsigned ah[4][4], al[4][4], bh[4][2], bl[4][2];
#pragma unroll
      for (int mt = 0; mt < 4; mt++) {
        int r0 = (wm * 64 + mt * 16 + qr) * 20 + ks + qc;
        int r1 = r0 + 8 * 20;
        ah[mt][0] = AsH[r0];     ah[mt][1] = AsH[r1];
        ah[mt][2] = AsH[r0 + 4]; ah[mt][3] = AsH[r1 + 4];
        al[mt][0] = AsL[r0];     al[mt][1] = AsL[r1];
        al[mt][2] = AsL[r0 + 4]; al[mt][3] = AsL[r1 + 4];
      }
#pragma unroll
      for (int nt = 0; nt < 4; nt++) {
        int c0 = (wn * 32 + nt * 8 + qr) * 20 + ks + qc;
        bh[nt][0] = BsH[c0]; bh[nt][1] = BsH[c0 + 4];
        bl[nt][0] = BsL[c0]; bl[nt][1] = BsL[c0 + 4];
      }
#pragma unroll
      for (int mt = 0; mt < 4; mt++)
#pragma unroll
        for (int nt = 0; nt < 4; nt++) {
          mma8(acc[mt][nt], ah[mt], bl[nt]);   // small terms first
          mma8(acc[mt][nt], al[mt], bh[nt]);
          mma8(acc[mt][nt], ah[mt], bh[nt]);
        }
    }
    __syncthreads();
  }

  // ---------- fused epilogue ----------
  float bcol[8]; int colg[8];
#pragma unroll
  for (int j = 0; j < 8; j++) {
    int nt = j >> 1, cc = j & 1;
    int col = colBase + wn * 32 + nt * 8 + qc * 2 + cc;
    colg[j] = col;
    bcol[j] = bias[col];
  }
  float* rmg = (float*)dsm;            // [128][4]
  int*   rix = (int*)(dsm + 512);
  float* rml = (float*)(dsm + 1024);
  float* rZf = (float*)(dsm + 1536);
  float* rSf = (float*)(dsm + 2048);

#pragma unroll
  for (int mt = 0; mt < 4; mt++) {
#pragma unroll
    for (int rg = 0; rg < 2; rg++) {
      int lrow = wm * 64 + mt * 16 + qr + rg * 8;
      int grow = rowBase + lrow;
      float l[8];
      float lml = -INFINITY;
#pragma unroll
      for (int j = 0; j < 8; j++) {
        int nt = j >> 1, cc = j & 1;
        l[j] = acc[mt][nt][rg * 2 + cc] + bcol[j];
        lml = fmaxf(lml, l[j]);
      }
      float best = -INFINITY; int bidx = 0x7fffffff;
      float Z = 0.f, S = 0.f;
#pragma unroll
      for (int j = 0; j < 8; j++) {
        unsigned o0, o1;
        tf2x32(k1a, k1b, 0u, (unsigned)(grow * VOC + colg[j]), o0, o1);
        unsigned rb = o0 ^ o1;
        float u = __uint_as_float((rb >> 9) | 0x3f800000u) - 1.0f;
        u = fmaxf(u, F_TINY);
        float g = -logf(-logf(u));
        float v = l[j] + g;
        if (v > best) { best = v; bidx = colg[j]; }
        float e = expf(l[j] - lml);
        Z += e; S += e * l[j];
      }
#pragma unroll
      for (int off = 1; off <= 2; off <<= 1) {
        float omg = __shfl_xor_sync(0xffffffffu, best, off);
        int   oix = __shfl_xor_sync(0xffffffffu, bidx, off);
        float oml = __shfl_xor_sync(0xffffffffu, lml, off);
        float oZ  = __shfl_xor_sync(0xffffffffu, Z, off);
        float oS  = __shfl_xor_sync(0xffffffffu, S, off);
        if (omg > best || (omg == best && oix < bidx)) { best = omg; bidx = oix; }
        float M = fmaxf(lml, oml);
        float w1 = expf(lml - M), w2 = expf(oml - M);
        Z = Z * w1 + oZ * w2;
        S = S * w1 + oS * w2;
        lml = M;
      }
      if (qc == 0) {
        rmg[lrow * 4 + wn] = best; rix[lrow * 4 + wn] = bidx;
        rml[lrow * 4 + wn] = lml;  rZf[lrow * 4 + wn] = Z;
        rSf[lrow * 4 + wn] = S;
      }
    }
  }
  __syncthreads();
  if (tid < 128) {
    int lrow = tid;
    float mg = rmg[lrow * 4]; int idx = rix[lrow * 4];
    float ml = rml[lrow * 4]; float Z = rZf[lrow * 4]; float S = rSf[lrow * 4];
#pragma unroll
    for (int w = 1; w < 4; w++) {
      float omg = rmg[lrow * 4 + w]; int oix = rix[lrow * 4 + w];
      float oml = rml[lrow * 4 + w]; float oZ = rZf[lrow * 4 + w];
      float oS = rSf[lrow * 4 + w];
      if (omg > mg || (omg == mg && oix < idx)) { mg = omg; idx = oix; }
      float M = fmaxf(ml, oml);
      float w1 = expf(ml - M), w2 = expf(oml - M);
      Z = Z * w1 + oZ * w2;
      S = S * w1 + oS * w2;
      ml = M;
    }
    int pi = (rowBase + lrow) * NCHUNK + blockIdx.x;
    pmg[pi] = mg; pidx[pi] = idx; pml[pi] = ml; pZ[pi] = Z; pS[pi] = S;
  }
}

// ---------------- GRU pointwise update (+ tf32 split of h) ----------------
__device__ __forceinline__ float sigmoidf_(float x) { return 1.f / (1.f + expf(-x)); }

__global__ __launch_bounds__(256)
void gru_update_kernel(const float* __restrict__ gi, const float* __restrict__ gh,
                       const float* __restrict__ hprev, float* __restrict__ hnew,
                       float* __restrict__ hH, float* __restrict__ hL) {
  int i = blockIdx.x * blockDim.x + threadIdx.x;    // 512*512
  int b = i >> 9, j = i & 511;
  const float* gib = gi + (size_t)b * G3;
  const float* ghb = gh + (size_t)b * G3;
  float r = sigmoidf_(gib[j]        + ghb[j]);
  float z = sigmoidf_(gib[512 + j]  + ghb[512 + j]);
  float n = tanhf(gib[1024 + j] + r * ghb[1024 + j]);
  float h = (1.f - z) * n + z * hprev[i];
  hnew[i] = h;
  float hi = __uint_as_float(f2tf(h));
  hH[i] = hi;
  hL[i] = __uint_as_float(f2tf(h - hi));
}

__global__ void init_inp_kernel(const float* __restrict__ sos, float* __restrict__ inp) {
  int i = blockIdx.x * blockDim.x + threadIdx.x;    // 512*256
  inp[i] = sos[i & 255];
}

// ---------------- per-row finalize ----------------
__global__ __launch_bounds__(256)
void finalize_kernel(const float* __restrict__ h, const float* __restrict__ W_out,
                     const float* __restrict__ b_out, const float* __restrict__ W_stop,
                     const float* __restrict__ b_stop, const float* __restrict__ emb,
                     const float* __restrict__ pmg, const int* __restrict__ pidx,
                     const float* __restrict__ pml, const float* __restrict__ pZ,
                     const float* __restrict__ pS,
                     float* __restrict__ inp, float* __restrict__ out,
                     int t, unsigned k2a, unsigned k2b) {
  int b = blockIdx.x, tid = threadIdx.x;
  float mg = -INFINITY, ml = -INFINITY, Z = 0.f, S = 0.f;
  int idx = 0x7fffffff;
  if (tid < NCHUNK) {
    int p = b * NCHUNK + tid;
    mg = pmg[p]; idx = pidx[p]; ml = pml[p]; Z = pZ[p]; S = pS[p];
  }
#pragma unroll
  for (int off = 16; off > 0; off >>= 1) {
    float omg = __shfl_xor_sync(0xffffffffu, mg, off);
    int   oix = __shfl_xor_sync(0xffffffffu, idx, off);
    float oml = __shfl_xor_sync(0xffffffffu, ml, off);
    float oZ  = __shfl_xor_sync(0xffffffffu, Z, off);
    float oS  = __shfl_xor_sync(0xffffffffu, S, off);
    if (omg > mg || (omg == mg && oix < idx)) { mg = omg; idx = oix; }
    float M = fmaxf(ml, oml);
    if (M > -INFINITY) {
      float w1 = (ml  > -INFINITY) ? expf(ml  - M) : 0.f;
      float w2 = (oml > -INFINITY) ? expf(oml - M) : 0.f;
      Z = Z * w1 + oZ * w2;
      S = S * w1 + oS * w2;
      ml = M;
    }
  }
  __shared__ float smg[8]; __shared__ int sidx[8];
  __shared__ float sml[8], sZ[8], sS[8];
  __shared__ int s_symb; __shared__ float s_ml, s_Z, s_S;
  int wid = tid >> 5, lane = tid & 31;
  if (lane == 0) { smg[wid] = mg; sidx[wid] = idx; sml[wid] = ml; sZ[wid] = Z; sS[wid] = S; }
  __syncthreads();
  if (wid == 0) {
    if (lane < 8) { mg = smg[lane]; idx = sidx[lane]; ml = sml[lane]; Z = sZ[lane]; S = sS[lane]; }
    else { mg = -INFINITY; idx = 0x7fffffff; ml = -INFINITY; Z = 0.f; S = 0.f; }
#pragma unroll
    for (int off = 4; off > 0; off >>= 1) {
      float omg = __shfl_xor_sync(0xffffffffu, mg, off);
      int   oix = __shfl_xor_sync(0xffffffffu, idx, off);
      float oml = __shfl_xor_sync(0xffffffffu, ml, off);
      float oZ  = __shfl_xor_sync(0xffffffffu, Z, off);
      float oS  = __shfl_xor_sync(0xffffffffu, S, off);
      if (omg > mg || (omg == mg && oix < idx)) { mg = omg; idx = oix; }
      float M = fmaxf(ml, oml);
      if (M > -INFINITY) {
        float w1 = (ml  > -INFINITY) ? expf(ml  - M) : 0.f;
        float w2 = (oml > -INFINITY) ? expf(oml - M) : 0.f;
        Z = Z * w1 + oZ * w2;
        S = S * w1 + oS * w2;
        ml = M;
      }
    }
    if (lane == 0) { s_symb = idx; s_ml = ml; s_Z = Z; s_S = S; }
  }
  __syncthreads();
  int symb = s_symb;

  __shared__ float r1[256], r2[256];
  float a1 = 0.f, a2 = 0.f;
  const float* hrow = h + (size_t)b * HID;
  const float* wrow = W_out + (size_t)symb * HID;
#pragma unroll
  for (int k = tid; k < HID; k += 256) {
    float hv = hrow[k];
    a1 += hv * wrow[k];
    a2 += hv * W_stop[k];
  }
  r1[tid] = a1; r2[tid] = a2;
  __syncthreads();
  for (int s = 128; s > 0; s >>= 1) {
    if (tid < s) { r1[tid] += r1[tid + s]; r2[tid] += r2[tid + s]; }
    __syncthreads();
  }

  inp[(size_t)b * EMB + tid] = emb[(size_t)symb * EMB + tid];

  if (tid == 0) {
    float lse = s_ml + logf(s_Z);
    float ent = lse - s_S / s_Z;
    float lsymb = r1[0] + b_out[symb];
    float sl = r2[0] + b_stop[0];
    unsigned o0, o1;
    tf2x32(k2a, k2b, 0u, (unsigned)b, o0, o1);
    unsigned rb = o0 ^ o1;
    float u = __uint_as_float((rb >> 9) | 0x3f800000u) - 1.0f;
    float p = 1.f / (1.f + expf(-sl));
    int stop = (u < p) ? 1 : 0;
    float sp = fmaxf(sl, 0.f) + log1pf(expf(-fabsf(sl)));
    out[0 * BT + b * TT + t] = (float)symb;
    out[1 * BT + b * TT + t] = (float)stop;
    out[2 * BT + b * TT + t] = lsymb - lse;
    out[3 * BT + b * TT + t] = (float)stop * sl - sp;
    out[4 * BT + b * TT + t] = ent;
    out[5 * BT + b * TT + t] = sp - sl * p;
  }
}

// ---------------- host ----------------
extern "C" void kernel_launch(void* const* d_in, const int* in_sizes, int n_in,
                              void* d_out, int out_size) {
  const float* x       = (const float*)d_in[0];
  const float* agent_w = (const float*)d_in[1];
  const float* agent_b = (const float*)d_in[2];
  const float* sos     = (const float*)d_in[3];
  const float* emb     = (const float*)d_in[4];
  const float* W_ih    = (const float*)d_in[5];
  const float* W_hh    = (const float*)d_in[6];
  const float* b_ih    = (const float*)d_in[7];
  const float* b_hh    = (const float*)d_in[8];
  const float* W_out   = (const float*)d_in[9];
  const float* b_out   = (const float*)d_in[10];
  const float* W_stop  = (const float*)d_in[11];
  const float* b_stop  = (const float*)d_in[12];
  float* out = (float*)d_out;

  float *hA, *hB, *hH, *hL, *WoH, *WoL, *inp, *gi, *gh, *pmg, *pml, *pZ, *pS;
  int* pidx;
  cudaGetSymbolAddress((void**)&hA,  g_hA);
  cudaGetSymbolAddress((void**)&hB,  g_hB);
  cudaGetSymbolAddress((void**)&hH,  g_hH);
  cudaGetSymbolAddress((void**)&hL,  g_hL);
  cudaGetSymbolAddress((void**)&WoH, g_WoH);
  cudaGetSymbolAddress((void**)&WoL, g_WoL);
  cudaGetSymbolAddress((void**)&inp, g_inp);
  cudaGetSymbolAddress((void**)&gi,  g_gi);
  cudaGetSymbolAddress((void**)&gh,  g_gh);
  cudaGetSymbolAddress((void**)&pmg, g_pmg);
  cudaGetSymbolAddress((void**)&pidx, g_pidx);
  cudaGetSymbolAddress((void**)&pml, g_pml);
  cudaGetSymbolAddress((void**)&pZ,  g_pZ);
  cudaGetSymbolAddress((void**)&pS,  g_pS);

  cudaFuncSetAttribute(logits_mma_kernel,
                       cudaFuncAttributeMaxDynamicSharedMemorySize, 81920);

  // one-time per launch: split W_out into tf32 hi/lo
  split_kernel<<<(VOC * HID / 4) / 256, 256>>>(W_out, WoH, WoL);

  sgemm_bias_kernel<<<dim3(HID / 128, BATCH / 64), 256>>>(x, agent_w, agent_b, hA, NIN, HID);
  init_inp_kernel<<<(BATCH * EMB) / 256, 256>>>(sos, inp);

  for (int t = 0; t < TT; t++) {
    unsigned kt0, kt1, k1a, k1b, k2a, k2b;
    h_tf2x32(0u, 42u, 0u, (unsigned)t, &kt0, &kt1);
    h_tf2x32(kt0, kt1, 0u, 0u, &k1a, &k1b);
    h_tf2x32(kt0, kt1, 0u, 1u, &k2a, &k2b);

    const float* hp = (t & 1) ? hB : hA;
    float*       hn = (t & 1) ? hA : hB;

    dual_sgemm_kernel<<<dim3(G3 / 128, BATCH / 64, 2), 256>>>(
        inp, W_ih, b_ih, gi, hp, W_hh, b_hh, gh);
    gru_update_kernel<<<(BATCH * HID) / 256, 256>>>(gi, gh, hp, hn, hH, hL);
    logits_mma_kernel<<<dim3(VOC / 128, BATCH / 128), 256, 81920>>>(
        hH, hL, WoH, WoL, b_out, pmg, pidx, pml, pZ, pS, k1a, k1b);
    finalize_kernel<<<BATCH, 256>>>(hn, W_out, b_out, W_stop, b_stop, emb,
                                    pmg, pidx, pml, pZ, pS, inp, out, t, k2a, k2b);
  }
}

// round 16
// speedup vs baseline: 1.5002x; 1.4869x over previous
#include <cuda_runtime.h>
#include <stdint.h>
#include <math.h>

// Problem constants
#define BATCH 512
#define NIN   256
#define EMB   256
#define HID   512
#define VOC   32000
#define TT    32
#define G3    1536          // 3*HID
#define NCHUNK 250          // VOC / 128
#define BT    (BATCH*TT)
#define F_TINY 1.17549435e-38f

// logits kernel staging
#define NK      32          // 512 / 16
#define ASTRIDE 20          // padded row stride (floats) for BK=16
#define STAGEF  5120        // floats per stage: A 128*20 + B 128*20
#define NSTAGE  3
#define SMEM_LOGITS (NSTAGE * STAGEF * 4)   // 61440 bytes

// ---------------- device scratch (no allocations allowed) ----------------
__device__ float g_hA[BATCH*HID];
__device__ float g_hB[BATCH*HID];
__device__ float g_inp[BATCH*EMB];
__device__ float g_gi[BATCH*G3];
__device__ float g_gh[BATCH*G3];
__device__ float g_pmg[BATCH*NCHUNK];
__device__ int   g_pidx[BATCH*NCHUNK];
__device__ float g_pml[BATCH*NCHUNK];
__device__ float g_pZ[BATCH*NCHUNK];
__device__ float g_pS[BATCH*NCHUNK];

// ---------------- threefry2x32 (matches jax exactly) ----------------
__device__ __forceinline__ void tf2x32(unsigned k0, unsigned k1,
                                       unsigned c0, unsigned c1,
                                       unsigned &o0, unsigned &o1) {
  unsigned ks2 = k0 ^ k1 ^ 0x1BD11BDAu;
  unsigned x0 = c0 + k0, x1 = c1 + k1;
#define TFR(r) { x0 += x1; x1 = (x1 << (r)) | (x1 >> (32 - (r))); x1 ^= x0; }
  TFR(13) TFR(15) TFR(26) TFR(6)   x0 += k1;  x1 += ks2 + 1u;
  TFR(17) TFR(29) TFR(16) TFR(24)  x0 += ks2; x1 += k0 + 2u;
  TFR(13) TFR(15) TFR(26) TFR(6)   x0 += k0;  x1 += k1 + 3u;
  TFR(17) TFR(29) TFR(16) TFR(24)  x0 += k1;  x1 += ks2 + 4u;
  TFR(13) TFR(15) TFR(26) TFR(6)   x0 += ks2; x1 += k0 + 5u;
#undef TFR
  o0 = x0; o1 = x1;
}

static void h_tf2x32(unsigned k0, unsigned k1, unsigned c0, unsigned c1,
                     unsigned *o0, unsigned *o1) {
  unsigned ks2 = k0 ^ k1 ^ 0x1BD11BDAu;
  unsigned x0 = c0 + k0, x1 = c1 + k1;
#define TFRH(r) { x0 += x1; x1 = (x1 << (r)) | (x1 >> (32 - (r))); x1 ^= x0; }
  TFRH(13) TFRH(15) TFRH(26) TFRH(6)   x0 += k1;  x1 += ks2 + 1u;
  TFRH(17) TFRH(29) TFRH(16) TFRH(24)  x0 += ks2; x1 += k0 + 2u;
  TFRH(13) TFRH(15) TFRH(26) TFRH(6)   x0 += k0;  x1 += k1 + 3u;
  TFRH(17) TFRH(29) TFRH(16) TFRH(24)  x0 += k1;  x1 += ks2 + 4u;
  TFRH(13) TFRH(15) TFRH(26) TFRH(6)   x0 += ks2; x1 += k0 + 5u;
#undef TFRH
  *o0 = x0; *o1 = x1;
}

// ---------------- tf32 helpers ----------------
__device__ __forceinline__ unsigned f2tf(float f) {
  unsigned r; asm("cvt.rna.tf32.f32 %0, %1;" : "=r"(r) : "f"(f)); return r;
}
__device__ __forceinline__ void split2(float f, unsigned &h, unsigned &l) {
  h = f2tf(f);
  l = f2tf(f - __uint_as_float(h));
}
__device__ __forceinline__ void mma8(float c[4], const unsigned a[4], const unsigned b[2]) {
  asm volatile("mma.sync.aligned.m16n8k8.row.col.f32.tf32.tf32.f32 "
               "{%0,%1,%2,%3}, {%4,%5,%6,%7}, {%8,%9}, {%0,%1,%2,%3};"
               : "+f"(c[0]), "+f"(c[1]), "+f"(c[2]), "+f"(c[3])
               : "r"(a[0]), "r"(a[1]), "r"(a[2]), "r"(a[3]),
                 "r"(b[0]), "r"(b[1]));
}
__device__ __forceinline__ void cp16(unsigned smem_addr, const void* gptr) {
  asm volatile("cp.async.ca.shared.global [%0], [%1], 16;"
               :: "r"(smem_addr), "l"(gptr));
}

// ---------------- shared SGEMM mainloop (C = A[M,K] @ B[N,K]^T) ----------
#define SGEMM_MAINLOOP(A, Bm, K)                                             \
  float acc[8][4];                                                           \
  _Pragma("unroll")                                                          \
  for (int i = 0; i < 8; i++) { _Pragma("unroll")                            \
    for (int j = 0; j < 4; j++) acc[i][j] = 0.f; }                           \
  {                                                                          \
    const float* Aptr = (A) + (size_t)rowBase * (K);                         \
    const float* Bptr = (Bm) + (size_t)colBase * (K);                        \
    int ar = tid >> 2, akq = tid & 3;                                        \
    for (int k0 = 0; k0 < (K); k0 += 16) {                                   \
      float4 av = *(const float4*)(Aptr + (size_t)ar * (K) + k0 + akq * 4);  \
      As[akq*4+0][ar] = av.x; As[akq*4+1][ar] = av.y;                        \
      As[akq*4+2][ar] = av.z; As[akq*4+3][ar] = av.w;                        \
      _Pragma("unroll")                                                      \
      for (int li = 0; li < 2; li++) {                                       \
        int idx2 = tid + li * 256; int br = idx2 >> 2, bkq = idx2 & 3;       \
        float4 bv = *(const float4*)(Bptr + (size_t)br * (K) + k0 + bkq*4);  \
        Bs[bkq*4+0][br] = bv.x; Bs[bkq*4+1][br] = bv.y;                      \
        Bs[bkq*4+2][br] = bv.z; Bs[bkq*4+3][br] = bv.w;                      \
      }                                                                      \
      __syncthreads();                                                       \
      _Pragma("unroll")                                                      \
      for (int kk = 0; kk < 16; kk++) {                                      \
        float a[8];                                                          \
        _Pragma("unroll")                                                    \
        for (int i = 0; i < 8; i++) a[i] = As[kk][ry*8+i];                   \
        float4 bq = *(const float4*)(&Bs[kk][cx*4]);                         \
        float bb[4] = {bq.x, bq.y, bq.z, bq.w};                              \
        _Pragma("unroll")                                                    \
        for (int i = 0; i < 8; i++) { _Pragma("unroll")                      \
          for (int j = 0; j < 4; j++) acc[i][j] += a[i] * bb[j]; }           \
      }                                                                      \
      __syncthreads();                                                       \
    }                                                                        \
  }

__global__ __launch_bounds__(256)
void sgemm_bias_kernel(const float* __restrict__ A, const float* __restrict__ Bm,
                       const float* __restrict__ bias, float* __restrict__ C,
                       int K, int N) {
  __shared__ __align__(16) float As[16][65];
  __shared__ __align__(16) float Bs[16][132];
  int tid = threadIdx.x;
  int cx = tid & 31, ry = tid >> 5;
  int rowBase = blockIdx.y * 64;
  int colBase = blockIdx.x * 128;
  SGEMM_MAINLOOP(A, Bm, K)
  int col = colBase + cx * 4;
  float4 b4 = *(const float4*)(bias + col);
#pragma unroll
  for (int i = 0; i < 8; i++) {
    int row = rowBase + ry * 8 + i;
    float4 o;
    o.x = acc[i][0] + b4.x; o.y = acc[i][1] + b4.y;
    o.z = acc[i][2] + b4.z; o.w = acc[i][3] + b4.w;
    *(float4*)(C + (size_t)row * N + col) = o;
  }
}

// Both small GRU GEMMs in one launch (z=0: gi, z=1: gh)
__global__ __launch_bounds__(256)
void dual_sgemm_kernel(const float* __restrict__ inp, const float* __restrict__ W_ih,
                       const float* __restrict__ b_ih, float* __restrict__ gi,
                       const float* __restrict__ hp, const float* __restrict__ W_hh,
                       const float* __restrict__ b_hh, float* __restrict__ gh) {
  __shared__ __align__(16) float As[16][65];
  __shared__ __align__(16) float Bs[16][132];
  int tid = threadIdx.x;
  int cx = tid & 31, ry = tid >> 5;
  int rowBase = blockIdx.y * 64;
  int colBase = blockIdx.x * 128;
  const float* A  = blockIdx.z ? hp   : inp;
  const float* Bm = blockIdx.z ? W_hh : W_ih;
  const float* bias = blockIdx.z ? b_hh : b_ih;
  float* C = blockIdx.z ? gh : gi;
  const int K = blockIdx.z ? HID : NIN;
  SGEMM_MAINLOOP(A, Bm, K)
  int col = colBase + cx * 4;
  float4 b4 = *(const float4*)(bias + col);
#pragma unroll
  for (int i = 0; i < 8; i++) {
    int row = rowBase + ry * 8 + i;
    float4 o;
    o.x = acc[i][0] + b4.x; o.y = acc[i][1] + b4.y;
    o.z = acc[i][2] + b4.z; o.w = acc[i][3] + b4.w;
    *(float4*)(C + (size_t)row * G3 + col) = o;
  }
}

// ========== logits GEMM v3: 3xTF32 mma.sync, raw fp32 staging ==========
// M=512, N=32000, K=512. CTA 128x128, BK=16, 8 warps (2x4), warp 64x32.
// 3-stage cp.async pipeline of RAW fp32 (20KB/stage); tf32 hi/lo split done
// in registers at fragment-read time. 2 CTAs/SM. Fused gumbel/softmax epilogue.
__global__ __launch_bounds__(256, 2)
void logits_mma_kernel(const float* __restrict__ A, const float* __restrict__ Bm,
                       const float* __restrict__ bias,
                       float* __restrict__ pmg, int* __restrict__ pidx,
                       float* __restrict__ pml, float* __restrict__ pZ,
                       float* __restrict__ pS,
                       unsigned k1a, unsigned k1b) {
  extern __shared__ __align__(16) float fsm[];   // NSTAGE * STAGEF floats

  const int tid = threadIdx.x;
  const int lane = tid & 31, wid = tid >> 5;
  const int wm = wid >> 2;       // 0..1 (64 rows each)
  const int wn = wid & 3;        // 0..3 (32 cols each)
  const int qr = lane >> 2;      // 0..7
  const int qc = lane & 3;       // 0..3
  const int rowBase = blockIdx.y * 128;
  const int colBase = blockIdx.x * 128;

  const float* Ag = A + (size_t)rowBase * HID;
  const float* Bg = Bm + (size_t)colBase * HID;
  unsigned sbase = (unsigned)__cvta_generic_to_shared(fsm);

  // load one BK=16 slab (A 128x16 + B 128x16 raw fp32) into stage stg
  auto load_stage = [&](int stg, int k0) {
#pragma unroll
    for (int i = 0; i < 4; i++) {
      int id = tid + i * 256;                 // 0..1023
      int tile = id >> 9, c = id & 511;
      int row = c >> 2, q = c & 3;
      const float* g = (tile ? Bg : Ag) + (size_t)row * HID + k0 + q * 4;
      unsigned sa = sbase + (unsigned)((stg * STAGEF + tile * 2560
                                        + row * ASTRIDE + q * 4) * 4);
      cp16(sa, g);
    }
    asm volatile("cp.async.commit_group;");
  };

  float acc[4][4][4];
#pragma unroll
  for (int mt = 0; mt < 4; mt++)
#pragma unroll
    for (int nt = 0; nt < 4; nt++)
#pragma unroll
      for (int r = 0; r < 4; r++) acc[mt][nt][r] = 0.f;

  load_stage(0, 0);
  load_stage(1, 16);
  for (int it = 0; it < NK; it++) {
    if (it + 1 < NK) asm volatile("cp.async.wait_group 1;");
    else             asm volatile("cp.async.wait_group 0;");
    __syncthreads();
    if (it + 2 < NK) load_stage((it + 2) % NSTAGE, (it + 2) * 16);

    const float* As = fsm + (it % NSTAGE) * STAGEF;
    const float* Bs = As + 2560;
#pragma unroll
    for (int ks = 0; ks < 16; ks += 8) {
      unsigned ah[4][4], al[4][4];
#pragma unroll
      for (int mt = 0; mt < 4; mt++) {
        int r0 = (wm * 64 + mt * 16 + qr) * ASTRIDE + ks + qc;
        int r1 = r0 + 8 * ASTRIDE;
        split2(As[r0],     ah[mt][0], al[mt][0]);
        split2(As[r1],     ah[mt][1], al[mt][1]);
        split2(As[r0 + 4], ah[mt][2], al[mt][2]);
        split2(As[r1 + 4], ah[mt][3], al[mt][3]);
      }
#pragma unroll
      for (int nt = 0; nt < 4; nt++) {
        int c0 = (wn * 32 + nt * 8 + qr) * ASTRIDE + ks + qc;
        unsigned bh[2], bl[2];
        split2(Bs[c0],     bh[0], bl[0]);
        split2(Bs[c0 + 4], bh[1], bl[1]);
#pragma unroll
        for (int mt = 0; mt < 4; mt++) {
          mma8(acc[mt][nt], ah[mt], bl);   // small terms first
          mma8(acc[mt][nt], al[mt], bh);
          mma8(acc[mt][nt], ah[mt], bh);
        }
      }
    }
    __syncthreads();
  }

  // ---------- fused epilogue (identical math to R5) ----------
  float bcol[8]; int colg[8];
#pragma unroll
  for (int j = 0; j < 8; j++) {
    int nt = j >> 1, cc = j & 1;
    int col = colBase + wn * 32 + nt * 8 + qc * 2 + cc;
    colg[j] = col;
    bcol[j] = bias[col];
  }
  // reduction scratch aliases stage smem (no As/Bs reads after mainloop)
  float* rmg = fsm;                  // [128][4]
  int*   rix = (int*)(fsm + 512);
  float* rml = fsm + 1024;
  float* rZf = fsm + 1536;
  float* rSf = fsm + 2048;

#pragma unroll
  for (int mt = 0; mt < 4; mt++) {
#pragma unroll
    for (int rg = 0; rg < 2; rg++) {
      int lrow = wm * 64 + mt * 16 + qr + rg * 8;
      int grow = rowBase + lrow;
      float l[8];
      float lml = -INFINITY;
#pragma unroll
      for (int j = 0; j < 8; j++) {
        int nt = j >> 1, cc = j & 1;
        l[j] = acc[mt][nt][rg * 2 + cc] + bcol[j];
        lml = fmaxf(lml, l[j]);
      }
      float best = -INFINITY; int bidx = 0x7fffffff;
      float Z = 0.f, S = 0.f;
#pragma unroll
      for (int j = 0; j < 8; j++) {
        unsigned o0, o1;
        tf2x32(k1a, k1b, 0u, (unsigned)(grow * VOC + colg[j]), o0, o1);
        unsigned rb = o0 ^ o1;               // JAX: bits1 ^ bits2
        float u = __uint_as_float((rb >> 9) | 0x3f800000u) - 1.0f;
        u = fmaxf(u, F_TINY);
        float g = -logf(-logf(u));
        float v = l[j] + g;
        if (v > best) { best = v; bidx = colg[j]; }
        float e = expf(l[j] - lml);
        Z += e; S += e * l[j];
      }
#pragma unroll
      for (int off = 1; off <= 2; off <<= 1) {
        float omg = __shfl_xor_sync(0xffffffffu, best, off);
        int   oix = __shfl_xor_sync(0xffffffffu, bidx, off);
        float oml = __shfl_xor_sync(0xffffffffu, lml, off);
        float oZ  = __shfl_xor_sync(0xffffffffu, Z, off);
        float oS  = __shfl_xor_sync(0xffffffffu, S, off);
        if (omg > best || (omg == best && oix < bidx)) { best = omg; bidx = oix; }
        float M = fmaxf(lml, oml);
        float w1 = expf(lml - M), w2 = expf(oml - M);
        Z = Z * w1 + oZ * w2;
        S = S * w1 + oS * w2;
        lml = M;
      }
      if (qc == 0) {
        rmg[lrow * 4 + wn] = best; rix[lrow * 4 + wn] = bidx;
        rml[lrow * 4 + wn] = lml;  rZf[lrow * 4 + wn] = Z;
        rSf[lrow * 4 + wn] = S;
      }
    }
  }
  __syncthreads();
  if (tid < 128) {
    int lrow = tid;
    float mg = rmg[lrow * 4]; int idx = rix[lrow * 4];
    float ml = rml[lrow * 4]; float Z = rZf[lrow * 4]; float S = rSf[lrow * 4];
#pragma unroll
    for (int w = 1; w < 4; w++) {
      float omg = rmg[lrow * 4 + w]; int oix = rix[lrow * 4 + w];
      float oml = rml[lrow * 4 + w]; float oZ = rZf[lrow * 4 + w];
      float oS = rSf[lrow * 4 + w];
      if (omg > mg || (omg == mg && oix < idx)) { mg = omg; idx = oix; }
      float M = fmaxf(ml, oml);
      float w1 = expf(ml - M), w2 = expf(oml - M);
      Z = Z * w1 + oZ * w2;
      S = S * w1 + oS * w2;
      ml = M;
    }
    int pi = (rowBase + lrow) * NCHUNK + blockIdx.x;
    pmg[pi] = mg; pidx[pi] = idx; pml[pi] = ml; pZ[pi] = Z; pS[pi] = S;
  }
}

// ---------------- GRU pointwise update ----------------
__device__ __forceinline__ float sigmoidf_(float x) { return 1.f / (1.f + expf(-x)); }

__global__ __launch_bounds__(256)
void gru_update_kernel(const float* __restrict__ gi, const float* __restrict__ gh,
                       const float* __restrict__ hprev, float* __restrict__ hnew) {
  int i = blockIdx.x * blockDim.x + threadIdx.x;    // 512*512
  int b = i >> 9, j = i & 511;
  const float* gib = gi + (size_t)b * G3;
  const float* ghb = gh + (size_t)b * G3;
  float r = sigmoidf_(gib[j]        + ghb[j]);
  float z = sigmoidf_(gib[512 + j]  + ghb[512 + j]);
  float n = tanhf(gib[1024 + j] + r * ghb[1024 + j]);
  hnew[i] = (1.f - z) * n + z * hprev[i];
}

__global__ void init_inp_kernel(const float* __restrict__ sos, float* __restrict__ inp) {
  int i = blockIdx.x * blockDim.x + threadIdx.x;    // 512*256
  inp[i] = sos[i & 255];
}

// ---------------- per-row finalize ----------------
__global__ __launch_bounds__(256)
void finalize_kernel(const float* __restrict__ h, const float* __restrict__ W_out,
                     const float* __restrict__ b_out, const float* __restrict__ W_stop,
                     const float* __restrict__ b_stop, const float* __restrict__ emb,
                     const float* __restrict__ pmg, const int* __restrict__ pidx,
                     const float* __restrict__ pml, const float* __restrict__ pZ,
                     const float* __restrict__ pS,
                     float* __restrict__ inp, float* __restrict__ out,
                     int t, unsigned k2a, unsigned k2b) {
  int b = blockIdx.x, tid = threadIdx.x;
  float mg = -INFINITY, ml = -INFINITY, Z = 0.f, S = 0.f;
  int idx = 0x7fffffff;
  if (tid < NCHUNK) {
    int p = b * NCHUNK + tid;
    mg = pmg[p]; idx = pidx[p]; ml = pml[p]; Z = pZ[p]; S = pS[p];
  }
#pragma unroll
  for (int off = 16; off > 0; off >>= 1) {
    float omg = __shfl_xor_sync(0xffffffffu, mg, off);
    int   oix = __shfl_xor_sync(0xffffffffu, idx, off);
    float oml = __shfl_xor_sync(0xffffffffu, ml, off);
    float oZ  = __shfl_xor_sync(0xffffffffu, Z, off);
    float oS  = __shfl_xor_sync(0xffffffffu, S, off);
    if (omg > mg || (omg == mg && oix < idx)) { mg = omg; idx = oix; }
    float M = fmaxf(ml, oml);
    if (M > -INFINITY) {
      float w1 = (ml  > -INFINITY) ? expf(ml  - M) : 0.f;
      float w2 = (oml > -INFINITY) ? expf(oml - M) : 0.f;
      Z = Z * w1 + oZ * w2;
      S = S * w1 + oS * w2;
      ml = M;
    }
  }
  __shared__ float smg[8]; __shared__ int sidx[8];
  __shared__ float sml[8], sZ[8], sS[8];
  __shared__ int s_symb; __shared__ float s_ml, s_Z, s_S;
  int wid = tid >> 5, lane = tid & 31;
  if (lane == 0) { smg[wid] = mg; sidx[wid] = idx; sml[wid] = ml; sZ[wid] = Z; sS[wid] = S; }
  __syncthreads();
  if (wid == 0) {
    if (lane < 8) { mg = smg[lane]; idx = sidx[lane]; ml = sml[lane]; Z = sZ[lane]; S = sS[lane]; }
    else { mg = -INFINITY; idx = 0x7fffffff; ml = -INFINITY; Z = 0.f; S = 0.f; }
#pragma unroll
    for (int off = 4; off > 0; off >>= 1) {
      float omg = __shfl_xor_sync(0xffffffffu, mg, off);
      int   oix = __shfl_xor_sync(0xffffffffu, idx, off);
      float oml = __shfl_xor_sync(0xffffffffu, ml, off);
      float oZ  = __shfl_xor_sync(0xffffffffu, Z, off);
      float oS  = __shfl_xor_sync(0xffffffffu, S, off);
      if (omg > mg || (omg == mg && oix < idx)) { mg = omg; idx = oix; }
      float M = fmaxf(ml, oml);
      if (M > -INFINITY) {
        float w1 = (ml  > -INFINITY) ? expf(ml  - M) : 0.f;
        float w2 = (oml > -INFINITY) ? expf(oml - M) : 0.f;
        Z = Z * w1 + oZ * w2;
        S = S * w1 + oS * w2;
        ml = M;
      }
    }
    if (lane == 0) { s_symb = idx; s_ml = ml; s_Z = Z; s_S = S; }
  }
  __syncthreads();
  int symb = s_symb;

  __shared__ float r1[256], r2[256];
  float a1 = 0.f, a2 = 0.f;
  const float* hrow = h + (size_t)b * HID;
  const float* wrow = W_out + (size_t)symb * HID;
#pragma unroll
  for (int k = tid; k < HID; k += 256) {
    float hv = hrow[k];
    a1 += hv * wrow[k];
    a2 += hv * W_stop[k];
  }
  r1[tid] = a1; r2[tid] = a2;
  __syncthreads();
  for (int s = 128; s > 0; s >>= 1) {
    if (tid < s) { r1[tid] += r1[tid + s]; r2[tid] += r2[tid + s]; }
    __syncthreads();
  }

  inp[(size_t)b * EMB + tid] = emb[(size_t)symb * EMB + tid];

  if (tid == 0) {
    float lse = s_ml + logf(s_Z);
    float ent = lse - s_S / s_Z;
    float lsymb = r1[0] + b_out[symb];
    float sl = r2[0] + b_stop[0];
    unsigned o0, o1;
    tf2x32(k2a, k2b, 0u, (unsigned)b, o0, o1);
    unsigned rb = o0 ^ o1;
    float u = __uint_as_float((rb >> 9) | 0x3f800000u) - 1.0f;
    float p = 1.f / (1.f + expf(-sl));
    int stop = (u < p) ? 1 : 0;
    float sp = fmaxf(sl, 0.f) + log1pf(expf(-fabsf(sl)));
    out[0 * BT + b * TT + t] = (float)symb;
    out[1 * BT + b * TT + t] = (float)stop;
    out[2 * BT + b * TT + t] = lsymb - lse;
    out[3 * BT + b * TT + t] = (float)stop * sl - sp;
    out[4 * BT + b * TT + t] = ent;
    out[5 * BT + b * TT + t] = sp - sl * p;
  }
}

// ---------------- host ----------------
extern "C" void kernel_launch(void* const* d_in, const int* in_sizes, int n_in,
                              void* d_out, int out_size) {
  const float* x       = (const float*)d_in[0];
  const float* agent_w = (const float*)d_in[1];
  const float* agent_b = (const float*)d_in[2];
  const float* sos     = (const float*)d_in[3];
  const float* emb     = (const float*)d_in[4];
  const float* W_ih    = (const float*)d_in[5];
  const float* W_hh    = (const float*)d_in[6];
  const float* b_ih    = (const float*)d_in[7];
  const float* b_hh    = (const float*)d_in[8];
  const float* W_out   = (const float*)d_in[9];
  const float* b_out   = (const float*)d_in[10];
  const float* W_stop  = (const float*)d_in[11];
  const float* b_stop  = (const float*)d_in[12];
  float* out = (float*)d_out;

  float *hA, *hB, *inp, *gi, *gh, *pmg, *pml, *pZ, *pS; int* pidx;
  cudaGetSymbolAddress((void**)&hA,  g_hA);
  cudaGetSymbolAddress((void**)&hB,  g_hB);
  cudaGetSymbolAddress((void**)&inp, g_inp);
  cudaGetSymbolAddress((void**)&gi,  g_gi);
  cudaGetSymbolAddress((void**)&gh,  g_gh);
  cudaGetSymbolAddress((void**)&pmg, g_pmg);
  cudaGetSymbolAddress((void**)&pidx, g_pidx);
  cudaGetSymbolAddress((void**)&pml, g_pml);
  cudaGetSymbolAddress((void**)&pZ,  g_pZ);
  cudaGetSymbolAddress((void**)&pS,  g_pS);

  cudaFuncSetAttribute(logits_mma_kernel,
                       cudaFuncAttributeMaxDynamicSharedMemorySize, SMEM_LOGITS);

  sgemm_bias_kernel<<<dim3(HID / 128, BATCH / 64), 256>>>(x, agent_w, agent_b, hA, NIN, HID);
  init_inp_kernel<<<(BATCH * EMB) / 256, 256>>>(sos, inp);

  for (int t = 0; t < TT; t++) {
    unsigned kt0, kt1, k1a, k1b, k2a, k2b;
    h_tf2x32(0u, 42u, 0u, (unsigned)t, &kt0, &kt1);
    h_tf2x32(kt0, kt1, 0u, 0u, &k1a, &k1b);
    h_tf2x32(kt0, kt1, 0u, 1u, &k2a, &k2b);

    const float* hp = (t & 1) ? hB : hA;
    float*       hn = (t & 1) ? hA : hB;

    dual_sgemm_kernel<<<dim3(G3 / 128, BATCH / 64, 2), 256>>>(
        inp, W_ih, b_ih, gi, hp, W_hh, b_hh, gh);
    gru_update_kernel<<<(BATCH * HID) / 256, 256>>>(gi, gh, hp, hn);
    logits_mma_kernel<<<dim3(VOC / 128, BATCH / 128), 256, SMEM_LOGITS>>>(
        hn, W_out, b_out, pmg, pidx, pml, pZ, pS, k1a, k1b);
    finalize_kernel<<<BATCH, 256>>>(hn, W_out, b_out, W_stop, b_stop, emb,
                                    pmg, pidx, pml, pZ, pS, inp, out, t, k2a, k2b);
  }
}